// round 10
// baseline (speedup 1.0000x reference)
#include <cuda_runtime.h>

#define MAXN 100000
#define MAXE 1600000
#define CAP  64

typedef unsigned long long ull;

// ---- scratch (device globals; no allocation allowed) ----
__device__ int    g_cnt[MAXN];                    // in-degree (excl. self loop)
__device__ float  g_dinv[MAXN];
__device__ int    g_bkt[(size_t)MAXN * CAP];      // per-dst src indices (25.6MB)
__device__ float  g_bw [(size_t)MAXN * CAP];      // per-dst edge weights (25.6MB)
__device__ float  g_h1[(size_t)MAXN * 64];        // X@W1
__device__ float  g_h2[(size_t)MAXN * 64];        // relu layer-1 output
__device__ float  g_h3[(size_t)MAXN * 40];        // h2@W2

// packed f32x2 FMA: d = a*b + d
#define FMA2(d, a, b) asm("fma.rn.f32x2 %0, %1, %2, %0;" : "+l"(d) : "l"(a), "l"(b))
#define PACK2(out, lo, hi) asm("mov.b64 %0, {%1, %2};" : "=l"(out) : "f"(lo), "f"(hi))

// ---------------- bucket build ----------------
__global__ void bucket_k(const int* __restrict__ ei, int E, int N) {
    int i = blockIdx.x * blockDim.x + threadIdx.x;
    if (i >= E) return;
    int s = ei[i];
    int d = ei[E + i];
    if ((unsigned)s >= (unsigned)N || (unsigned)d >= (unsigned)N) return;
    int pos = atomicAdd(g_cnt + d, 1);
    if (pos < CAP) g_bkt[(size_t)d * CAP + pos] = s;
}

__global__ void dinv_k(int N) {
    int i = blockIdx.x * blockDim.x + threadIdx.x;
    if (i < N) g_dinv[i] = rsqrtf((float)g_cnt[i] + 1.0f);  // +1 self loop
}

// per-slot edge weight: w = dinv[src]*dinv[dst]; one warp per node
__global__ void fillw_k(int N) {
    int wid = (blockIdx.x * blockDim.x + threadIdx.x) >> 5;
    int lane = threadIdx.x & 31;
    if (wid >= N) return;
    int deg = min(g_cnt[wid], CAP);
    float dn = g_dinv[wid];
    const int* bp = g_bkt + (size_t)wid * CAP;
    float* wp = g_bw + (size_t)wid * CAP;
    for (int j = lane; j < deg; j += 32)
        wp[j] = __ldg(g_dinv + bp[j]) * dn;
}

// ---------------- GEMM layer 1: g_h1 = X @ W1 (f32x2 packed) ----------------
__global__ __launch_bounds__(256) void gemm1_k(
    const float* __restrict__ X, const float* __restrict__ W, int N)
{
    __shared__ __align__(16) float Ws[128 * 64];
    for (int i = threadIdx.x; i < 128 * 64; i += 256) Ws[i] = W[i];
    __syncthreads();

    int r = blockIdx.x * 256 + threadIdx.x;
    if (r >= N) return;

    ull acc[32];
#pragma unroll
    for (int j = 0; j < 32; j++) acc[j] = 0ULL;

    const float4* xr = (const float4*)(X + (size_t)r * 128);
#pragma unroll 1
    for (int k4 = 0; k4 < 32; k4++) {
        float4 xv = xr[k4];
        ull xa, xb, xc, xd;
        PACK2(xa, xv.x, xv.x); PACK2(xb, xv.y, xv.y);
        PACK2(xc, xv.z, xv.z); PACK2(xd, xv.w, xv.w);
        const ulonglong2* w0 = (const ulonglong2*)(Ws + (k4 * 4 + 0) * 64);
        const ulonglong2* w1 = (const ulonglong2*)(Ws + (k4 * 4 + 1) * 64);
        const ulonglong2* w2 = (const ulonglong2*)(Ws + (k4 * 4 + 2) * 64);
        const ulonglong2* w3 = (const ulonglong2*)(Ws + (k4 * 4 + 3) * 64);
#pragma unroll
        for (int j = 0; j < 16; j++) {
            ulonglong2 a0 = w0[j]; FMA2(acc[2*j], xa, a0.x); FMA2(acc[2*j+1], xa, a0.y);
            ulonglong2 a1 = w1[j]; FMA2(acc[2*j], xb, a1.x); FMA2(acc[2*j+1], xb, a1.y);
            ulonglong2 a2 = w2[j]; FMA2(acc[2*j], xc, a2.x); FMA2(acc[2*j+1], xc, a2.y);
            ulonglong2 a3 = w3[j]; FMA2(acc[2*j], xd, a3.x); FMA2(acc[2*j+1], xd, a3.y);
        }
    }

    ulonglong2* Hp = (ulonglong2*)(g_h1 + (size_t)r * 64);
#pragma unroll
    for (int j = 0; j < 16; j++) {
        ulonglong2 v; v.x = acc[2*j]; v.y = acc[2*j+1];
        Hp[j] = v;
    }
}

// -------- gather layer 1: h2 = relu( sum_in h1[s]*w + h1[n]*dinv^2 + b1 )
// one warp per node; half h owns edges e+4h..e+4h+3; lane owns 4 fp32 feats
__global__ __launch_bounds__(256) void gather1_k(const float* __restrict__ b1, int N)
{
    int wid = (blockIdx.x * 256 + threadIdx.x) >> 5;
    int lane = threadIdx.x & 31;
    if (wid >= N) return;
    int n = wid;
    int half = lane >> 4;
    int hl = lane & 15;

    int deg = min(g_cnt[n], CAP);
    const int* bp = g_bkt + (size_t)n * CAP;
    const float* wp = g_bw + (size_t)n * CAP;

    float4 acc = make_float4(0.f, 0.f, 0.f, 0.f);
    int e = 0;
    for (; e + 7 < deg; e += 8) {
        int off = e + half * 4;
        int4   ss = *(const int4*)(bp + off);     // 4 edge indices, broadcast in half
        float4 ww = *(const float4*)(wp + off);   // 4 edge weights
        float4 v0 = *(const float4*)(g_h1 + (size_t)ss.x * 64 + hl * 4);
        float4 v1 = *(const float4*)(g_h1 + (size_t)ss.y * 64 + hl * 4);
        float4 v2 = *(const float4*)(g_h1 + (size_t)ss.z * 64 + hl * 4);
        float4 v3 = *(const float4*)(g_h1 + (size_t)ss.w * 64 + hl * 4);
        acc.x += v0.x * ww.x + v1.x * ww.y + v2.x * ww.z + v3.x * ww.w;
        acc.y += v0.y * ww.x + v1.y * ww.y + v2.y * ww.z + v3.y * ww.w;
        acc.z += v0.z * ww.x + v1.z * ww.y + v2.z * ww.z + v3.z * ww.w;
        acc.w += v0.w * ww.x + v1.w * ww.y + v2.w * ww.z + v3.w * ww.w;
    }
    for (int r = e + half; r < deg; r += 2) {
        int s0 = __ldg(bp + r);
        float w0 = __ldg(wp + r);
        float4 v0 = *(const float4*)(g_h1 + (size_t)s0 * 64 + hl * 4);
        acc.x += v0.x * w0; acc.y += v0.y * w0;
        acc.z += v0.z * w0; acc.w += v0.w * w0;
    }

    acc.x += __shfl_xor_sync(0xFFFFFFFFu, acc.x, 16);
    acc.y += __shfl_xor_sync(0xFFFFFFFFu, acc.y, 16);
    acc.z += __shfl_xor_sync(0xFFFFFFFFu, acc.z, 16);
    acc.w += __shfl_xor_sync(0xFFFFFFFFu, acc.w, 16);

    if (half == 0) {
        float dn = g_dinv[n];
        float sl = dn * dn;
        float4 h = *(const float4*)(g_h1 + (size_t)n * 64 + hl * 4);
        float4 bb = *(const float4*)(b1 + hl * 4);
        float4 o;
        o.x = fmaxf(acc.x + h.x * sl + bb.x, 0.f);
        o.y = fmaxf(acc.y + h.y * sl + bb.y, 0.f);
        o.z = fmaxf(acc.z + h.z * sl + bb.z, 0.f);
        o.w = fmaxf(acc.w + h.w * sl + bb.w, 0.f);
        *(float4*)(g_h2 + (size_t)n * 64 + hl * 4) = o;
    }
}

// ---------------- GEMM layer 2: g_h3 = h2 @ W2 (f32x2 packed) ----------------
__global__ __launch_bounds__(256) void gemm2_k(const float* __restrict__ W, int N)
{
    __shared__ __align__(16) float Ws[64 * 40];
    for (int i = threadIdx.x; i < 64 * 40; i += 256) Ws[i] = W[i];
    __syncthreads();

    int r = blockIdx.x * 256 + threadIdx.x;
    if (r >= N) return;

    ull acc[20];
#pragma unroll
    for (int j = 0; j < 20; j++) acc[j] = 0ULL;

    const float4* xr = (const float4*)(g_h2 + (size_t)r * 64);
#pragma unroll 1
    for (int k4 = 0; k4 < 16; k4++) {
        float4 xv = xr[k4];
        ull xa, xb, xc, xd;
        PACK2(xa, xv.x, xv.x); PACK2(xb, xv.y, xv.y);
        PACK2(xc, xv.z, xv.z); PACK2(xd, xv.w, xv.w);
        const ulonglong2* w0 = (const ulonglong2*)(Ws + (k4 * 4 + 0) * 40);
        const ulonglong2* w1 = (const ulonglong2*)(Ws + (k4 * 4 + 1) * 40);
        const ulonglong2* w2 = (const ulonglong2*)(Ws + (k4 * 4 + 2) * 40);
        const ulonglong2* w3 = (const ulonglong2*)(Ws + (k4 * 4 + 3) * 40);
#pragma unroll
        for (int j = 0; j < 10; j++) {
            ulonglong2 a0 = w0[j]; FMA2(acc[2*j], xa, a0.x); FMA2(acc[2*j+1], xa, a0.y);
            ulonglong2 a1 = w1[j]; FMA2(acc[2*j], xb, a1.x); FMA2(acc[2*j+1], xb, a1.y);
            ulonglong2 a2 = w2[j]; FMA2(acc[2*j], xc, a2.x); FMA2(acc[2*j+1], xc, a2.y);
            ulonglong2 a3 = w3[j]; FMA2(acc[2*j], xd, a3.x); FMA2(acc[2*j+1], xd, a3.y);
        }
    }

    ulonglong2* Hp = (ulonglong2*)(g_h3 + (size_t)r * 40);
#pragma unroll
    for (int j = 0; j < 10; j++) {
        ulonglong2 v; v.x = acc[2*j]; v.y = acc[2*j+1];
        Hp[j] = v;
    }
}

// -------- gather layer 2 + bias + log_softmax --------
// one warp per node; lanes 0..19 own features [2*lane, 2*lane+1] of 40
__global__ __launch_bounds__(256) void gather2_k(float* __restrict__ out,
                                                 const float* __restrict__ b2, int N)
{
    int wid = (blockIdx.x * 256 + threadIdx.x) >> 5;
    int lane = threadIdx.x & 31;
    if (wid >= N) return;
    int n = wid;
    bool act = lane < 20;
    int fo = act ? lane * 2 : 0;

    int deg = min(g_cnt[n], CAP);
    const int* bp = g_bkt + (size_t)n * CAP;
    const float* wp = g_bw + (size_t)n * CAP;

    float2 a0 = make_float2(0.f, 0.f), a1 = make_float2(0.f, 0.f);
    float2 a2 = make_float2(0.f, 0.f), a3 = make_float2(0.f, 0.f);
    int e = 0;
    for (; e + 3 < deg; e += 4) {
        int4   ss = *(const int4*)(bp + e);
        float4 ww = *(const float4*)(wp + e);
        float2 v0 = *(const float2*)(g_h3 + (size_t)ss.x * 40 + fo);
        float2 v1 = *(const float2*)(g_h3 + (size_t)ss.y * 40 + fo);
        float2 v2 = *(const float2*)(g_h3 + (size_t)ss.z * 40 + fo);
        float2 v3 = *(const float2*)(g_h3 + (size_t)ss.w * 40 + fo);
        a0.x += v0.x * ww.x; a0.y += v0.y * ww.x;
        a1.x += v1.x * ww.y; a1.y += v1.y * ww.y;
        a2.x += v2.x * ww.z; a2.y += v2.y * ww.z;
        a3.x += v3.x * ww.w; a3.y += v3.y * ww.w;
    }
    for (; e < deg; e++) {
        int s0 = __ldg(bp + e);
        float w0 = __ldg(wp + e);
        float2 v0 = *(const float2*)(g_h3 + (size_t)s0 * 40 + fo);
        a0.x += v0.x * w0; a0.y += v0.y * w0;
    }

    float dn = g_dinv[n];
    float sl = dn * dn;
    float2 h = *(const float2*)(g_h3 + (size_t)n * 40 + fo);
    float2 bb = *(const float2*)(b2 + fo);
    float vx = a0.x + a1.x + a2.x + a3.x + h.x * sl + bb.x;
    float vy = a0.y + a1.y + a2.y + a3.y + h.y * sl + bb.y;

    float m = act ? fmaxf(vx, vy) : -3.0e38f;
#pragma unroll
    for (int o = 16; o > 0; o >>= 1) m = fmaxf(m, __shfl_xor_sync(0xFFFFFFFFu, m, o));
    float s = act ? (expf(vx - m) + expf(vy - m)) : 0.f;
#pragma unroll
    for (int o = 16; o > 0; o >>= 1) s += __shfl_xor_sync(0xFFFFFFFFu, s, o);
    float lse = m + logf(s);

    if (act)
        *(float2*)(out + (size_t)n * 40 + fo) = make_float2(vx - lse, vy - lse);
}

extern "C" void kernel_launch(void* const* d_in, const int* in_sizes, int n_in,
                              void* d_out, int out_size)
{
    const float* x  = (const float*)d_in[0];
    const int*   ei = (const int*)d_in[1];      // int32 (JAX x64 disabled)
    const float* W1 = (const float*)d_in[2];
    const float* b1 = (const float*)d_in[3];
    const float* W2 = (const float*)d_in[4];
    const float* b2 = (const float*)d_in[5];
    float* out = (float*)d_out;

    int N = in_sizes[0] / 128;
    int E = in_sizes[1] / 2;
    const int T = 256;

    // bucket build + weights
    void* cnt_ptr = 0;
    cudaGetSymbolAddress(&cnt_ptr, g_cnt);
    cudaMemsetAsync(cnt_ptr, 0, (size_t)N * sizeof(int));
    bucket_k<<<(E + T - 1) / T, T>>>(ei, E, N);
    dinv_k<<<(N + T - 1) / T, T>>>(N);
    fillw_k<<<(N * 32 + T - 1) / T, T>>>(N);

    // layer 1
    gemm1_k<<<(N + T - 1) / T, T>>>(x, W1, N);
    gather1_k<<<(N * 32 + T - 1) / T, T>>>(b1, N);

    // layer 2
    gemm2_k<<<(N + T - 1) / T, T>>>(W2, N);
    gather2_k<<<(N * 32 + T - 1) / T, T>>>(out, b2, N);
}

// round 12
// speedup vs baseline: 1.0437x; 1.0437x over previous
#include <cuda_runtime.h>
#include <cuda_fp16.h>
#include <mma.h>

using namespace nvcuda;

#define MAXN 100000
#define MAXE 1600000
#define CAP  64

typedef unsigned long long ull;

// ---- scratch (device globals; no allocation allowed) ----
__device__ int    g_cnt[MAXN];                    // in-degree (excl. self loop)
__device__ float  g_dinv[MAXN];
__device__ int    g_bkt[(size_t)MAXN * CAP];      // per-dst src indices (25.6MB)
__device__ float  g_bw [(size_t)MAXN * CAP];      // per-dst edge weights (25.6MB)
__device__ __half g_xh[(size_t)MAXN * 128];       // fp16 copy of X (25.6MB)
__device__ __half g_wh[128 * 64];                 // fp16 copy of W1
__device__ float  g_h1[(size_t)MAXN * 64];        // X@W1 (fp32)
__device__ float  g_h2[(size_t)MAXN * 64];        // relu layer-1 output
__device__ float  g_h3[(size_t)MAXN * 40];        // h2@W2

// packed f32x2 FMA: d = a*b + d
#define FMA2(d, a, b) asm("fma.rn.f32x2 %0, %1, %2, %0;" : "+l"(d) : "l"(a), "l"(b))
#define PACK2(out, lo, hi) asm("mov.b64 %0, {%1, %2};" : "=l"(out) : "f"(lo), "f"(hi))

struct __align__(16) H8 { __half2 a, b, c, d; };

// ---------------- bucket build ----------------
__global__ void bucket_k(const int* __restrict__ ei, int E, int N) {
    int i = blockIdx.x * blockDim.x + threadIdx.x;
    if (i >= E) return;
    int s = ei[i];
    int d = ei[E + i];
    if ((unsigned)s >= (unsigned)N || (unsigned)d >= (unsigned)N) return;
    int pos = atomicAdd(g_cnt + d, 1);
    if (pos < CAP) g_bkt[(size_t)d * CAP + pos] = s;
}

__global__ void dinv_k(int N) {
    int i = blockIdx.x * blockDim.x + threadIdx.x;
    if (i < N) g_dinv[i] = rsqrtf((float)g_cnt[i] + 1.0f);  // +1 self loop
}

// per-slot edge weight: w = dinv[src]*dinv[dst]; one warp per node
__global__ void fillw_k(int N) {
    int wid = (blockIdx.x * blockDim.x + threadIdx.x) >> 5;
    int lane = threadIdx.x & 31;
    if (wid >= N) return;
    int deg = min(g_cnt[wid], CAP);
    float dn = g_dinv[wid];
    const int* bp = g_bkt + (size_t)wid * CAP;
    float* wp = g_bw + (size_t)wid * CAP;
    for (int j = lane; j < deg; j += 32)
        wp[j] = __ldg(g_dinv + bp[j]) * dn;
}

// ---------------- fp16 conversions ----------------
__global__ void cvtX_k(const float* __restrict__ X, int n8) {   // n8 = N*128/8
    int i = blockIdx.x * blockDim.x + threadIdx.x;
    if (i >= n8) return;
    float4 a = ((const float4*)X)[2 * i];
    float4 b = ((const float4*)X)[2 * i + 1];
    H8 h;
    h.a = __floats2half2_rn(a.x, a.y);
    h.b = __floats2half2_rn(a.z, a.w);
    h.c = __floats2half2_rn(b.x, b.y);
    h.d = __floats2half2_rn(b.z, b.w);
    ((H8*)g_xh)[i] = h;
}

__global__ void cvtW_k(const float* __restrict__ W) {
    for (int i = threadIdx.x; i < 128 * 64; i += blockDim.x)
        g_wh[i] = __float2half(W[i]);
}

// ---------------- GEMM layer 1 via HMMA: g_h1 = Xh @ Wh ----------------
// 128 threads = 4 warps; block handles 16 rows x 64 cols; warp w does col tile w
__global__ __launch_bounds__(128) void gemm1_wmma_k(int N) {
    int warp = threadIdx.x >> 5;
    size_t mt = blockIdx.x;             // row tile (16 rows)

    wmma::fragment<wmma::matrix_a, 16, 16, 16, __half, wmma::row_major> a;
    wmma::fragment<wmma::matrix_b, 16, 16, 16, __half, wmma::row_major> b;
    wmma::fragment<wmma::accumulator, 16, 16, 16, float> c;
    wmma::fill_fragment(c, 0.0f);

    const __half* xbase = g_xh + mt * 16 * 128;
    const __half* wbase = g_wh + warp * 16;
#pragma unroll
    for (int k = 0; k < 8; k++) {
        wmma::load_matrix_sync(a, xbase + k * 16, 128);
        wmma::load_matrix_sync(b, wbase + (size_t)k * 16 * 64, 64);
        wmma::mma_sync(c, a, b, c);
    }
    wmma::store_matrix_sync(g_h1 + mt * 16 * 64 + warp * 16, c, 64, wmma::mem_row_major);
}

// -------- gather layer 1: h2 = relu( sum_in h1[s]*w + h1[n]*dinv^2 + b1 )
__global__ __launch_bounds__(256) void gather1_k(const float* __restrict__ b1, int N)
{
    int wid = (blockIdx.x * 256 + threadIdx.x) >> 5;
    int lane = threadIdx.x & 31;
    if (wid >= N) return;
    int n = wid;
    int half = lane >> 4;
    int hl = lane & 15;

    int deg = min(g_cnt[n], CAP);
    const int* bp = g_bkt + (size_t)n * CAP;
    const float* wp = g_bw + (size_t)n * CAP;

    float4 acc = make_float4(0.f, 0.f, 0.f, 0.f);
    int e = 0;
    for (; e + 7 < deg; e += 8) {
        int off = e + half * 4;
        int4   ss = *(const int4*)(bp + off);
        float4 ww = *(const float4*)(wp + off);
        float4 v0 = *(const float4*)(g_h1 + (size_t)ss.x * 64 + hl * 4);
        float4 v1 = *(const float4*)(g_h1 + (size_t)ss.y * 64 + hl * 4);
        float4 v2 = *(const float4*)(g_h1 + (size_t)ss.z * 64 + hl * 4);
        float4 v3 = *(const float4*)(g_h1 + (size_t)ss.w * 64 + hl * 4);
        acc.x += v0.x * ww.x + v1.x * ww.y + v2.x * ww.z + v3.x * ww.w;
        acc.y += v0.y * ww.x + v1.y * ww.y + v2.y * ww.z + v3.y * ww.w;
        acc.z += v0.z * ww.x + v1.z * ww.y + v2.z * ww.z + v3.z * ww.w;
        acc.w += v0.w * ww.x + v1.w * ww.y + v2.w * ww.z + v3.w * ww.w;
    }
    for (int r = e + half; r < deg; r += 2) {
        int s0 = __ldg(bp + r);
        float w0 = __ldg(wp + r);
        float4 v0 = *(const float4*)(g_h1 + (size_t)s0 * 64 + hl * 4);
        acc.x += v0.x * w0; acc.y += v0.y * w0;
        acc.z += v0.z * w0; acc.w += v0.w * w0;
    }

    acc.x += __shfl_xor_sync(0xFFFFFFFFu, acc.x, 16);
    acc.y += __shfl_xor_sync(0xFFFFFFFFu, acc.y, 16);
    acc.z += __shfl_xor_sync(0xFFFFFFFFu, acc.z, 16);
    acc.w += __shfl_xor_sync(0xFFFFFFFFu, acc.w, 16);

    if (half == 0) {
        float dn = g_dinv[n];
        float sl = dn * dn;
        float4 h = *(const float4*)(g_h1 + (size_t)n * 64 + hl * 4);
        float4 bb = *(const float4*)(b1 + hl * 4);
        float4 o;
        o.x = fmaxf(acc.x + h.x * sl + bb.x, 0.f);
        o.y = fmaxf(acc.y + h.y * sl + bb.y, 0.f);
        o.z = fmaxf(acc.z + h.z * sl + bb.z, 0.f);
        o.w = fmaxf(acc.w + h.w * sl + bb.w, 0.f);
        *(float4*)(g_h2 + (size_t)n * 64 + hl * 4) = o;
    }
}

// ---------------- GEMM layer 2: g_h3 = h2 @ W2 (f32x2 packed) ----------------
__global__ __launch_bounds__(256) void gemm2_k(const float* __restrict__ W, int N)
{
    __shared__ __align__(16) float Ws[64 * 40];
    for (int i = threadIdx.x; i < 64 * 40; i += 256) Ws[i] = W[i];
    __syncthreads();

    int r = blockIdx.x * 256 + threadIdx.x;
    if (r >= N) return;

    ull acc[20];
#pragma unroll
    for (int j = 0; j < 20; j++) acc[j] = 0ULL;

    const float4* xr = (const float4*)(g_h2 + (size_t)r * 64);
#pragma unroll 1
    for (int k4 = 0; k4 < 16; k4++) {
        float4 xv = xr[k4];
        ull xa, xb, xc, xd;
        PACK2(xa, xv.x, xv.x); PACK2(xb, xv.y, xv.y);
        PACK2(xc, xv.z, xv.z); PACK2(xd, xv.w, xv.w);
        const ulonglong2* w0 = (const ulonglong2*)(Ws + (k4 * 4 + 0) * 40);
        const ulonglong2* w1 = (const ulonglong2*)(Ws + (k4 * 4 + 1) * 40);
        const ulonglong2* w2 = (const ulonglong2*)(Ws + (k4 * 4 + 2) * 40);
        const ulonglong2* w3 = (const ulonglong2*)(Ws + (k4 * 4 + 3) * 40);
#pragma unroll
        for (int j = 0; j < 10; j++) {
            ulonglong2 a0 = w0[j]; FMA2(acc[2*j], xa, a0.x); FMA2(acc[2*j+1], xa, a0.y);
            ulonglong2 a1 = w1[j]; FMA2(acc[2*j], xb, a1.x); FMA2(acc[2*j+1], xb, a1.y);
            ulonglong2 a2 = w2[j]; FMA2(acc[2*j], xc, a2.x); FMA2(acc[2*j+1], xc, a2.y);
            ulonglong2 a3 = w3[j]; FMA2(acc[2*j], xd, a3.x); FMA2(acc[2*j+1], xd, a3.y);
        }
    }

    ulonglong2* Hp = (ulonglong2*)(g_h3 + (size_t)r * 40);
#pragma unroll
    for (int j = 0; j < 10; j++) {
        ulonglong2 v; v.x = acc[2*j]; v.y = acc[2*j+1];
        Hp[j] = v;
    }
}

// -------- gather layer 2 + bias + log_softmax --------
__global__ __launch_bounds__(256) void gather2_k(float* __restrict__ out,
                                                 const float* __restrict__ b2, int N)
{
    int wid = (blockIdx.x * 256 + threadIdx.x) >> 5;
    int lane = threadIdx.x & 31;
    if (wid >= N) return;
    int n = wid;
    bool act = lane < 20;
    int fo = act ? lane * 2 : 0;

    int deg = min(g_cnt[n], CAP);
    const int* bp = g_bkt + (size_t)n * CAP;
    const float* wp = g_bw + (size_t)n * CAP;

    float2 a0 = make_float2(0.f, 0.f), a1 = make_float2(0.f, 0.f);
    float2 a2 = make_float2(0.f, 0.f), a3 = make_float2(0.f, 0.f);
    int e = 0;
    for (; e + 3 < deg; e += 4) {
        int4   ss = *(const int4*)(bp + e);
        float4 ww = *(const float4*)(wp + e);
        float2 v0 = *(const float2*)(g_h3 + (size_t)ss.x * 40 + fo);
        float2 v1 = *(const float2*)(g_h3 + (size_t)ss.y * 40 + fo);
        float2 v2 = *(const float2*)(g_h3 + (size_t)ss.z * 40 + fo);
        float2 v3 = *(const float2*)(g_h3 + (size_t)ss.w * 40 + fo);
        a0.x += v0.x * ww.x; a0.y += v0.y * ww.x;
        a1.x += v1.x * ww.y; a1.y += v1.y * ww.y;
        a2.x += v2.x * ww.z; a2.y += v2.y * ww.z;
        a3.x += v3.x * ww.w; a3.y += v3.y * ww.w;
    }
    for (; e < deg; e++) {
        int s0 = __ldg(bp + e);
        float w0 = __ldg(wp + e);
        float2 v0 = *(const float2*)(g_h3 + (size_t)s0 * 40 + fo);
        a0.x += v0.x * w0; a0.y += v0.y * w0;
    }

    float dn = g_dinv[n];
    float sl = dn * dn;
    float2 h = *(const float2*)(g_h3 + (size_t)n * 40 + fo);
    float2 bb = *(const float2*)(b2 + fo);
    float vx = a0.x + a1.x + a2.x + a3.x + h.x * sl + bb.x;
    float vy = a0.y + a1.y + a2.y + a3.y + h.y * sl + bb.y;

    float m = act ? fmaxf(vx, vy) : -3.0e38f;
#pragma unroll
    for (int o = 16; o > 0; o >>= 1) m = fmaxf(m, __shfl_xor_sync(0xFFFFFFFFu, m, o));
    float s = act ? (expf(vx - m) + expf(vy - m)) : 0.f;
#pragma unroll
    for (int o = 16; o > 0; o >>= 1) s += __shfl_xor_sync(0xFFFFFFFFu, s, o);
    float lse = m + logf(s);

    if (act)
        *(float2*)(out + (size_t)n * 40 + fo) = make_float2(vx - lse, vy - lse);
}

extern "C" void kernel_launch(void* const* d_in, const int* in_sizes, int n_in,
                              void* d_out, int out_size)
{
    const float* x  = (const float*)d_in[0];
    const int*   ei = (const int*)d_in[1];      // int32 (JAX x64 disabled)
    const float* W1 = (const float*)d_in[2];
    const float* b1 = (const float*)d_in[3];
    const float* W2 = (const float*)d_in[4];
    const float* b2 = (const float*)d_in[5];
    float* out = (float*)d_out;

    int N = in_sizes[0] / 128;
    int E = in_sizes[1] / 2;
    const int T = 256;

    // bucket build + weights (also converts X/W1 to fp16 in parallel order)
    void* cnt_ptr = 0;
    cudaGetSymbolAddress(&cnt_ptr, g_cnt);
    cudaMemsetAsync(cnt_ptr, 0, (size_t)N * sizeof(int));
    cvtX_k<<<(N * 16 + T - 1) / T, T>>>(x, N * 16);    // N*128/8 groups
    cvtW_k<<<1, 256>>>(W1);
    bucket_k<<<(E + T - 1) / T, T>>>(ei, E, N);
    dinv_k<<<(N + T - 1) / T, T>>>(N);
    fillw_k<<<(N * 32 + T - 1) / T, T>>>(N);

    // layer 1: HMMA GEMM + gather
    gemm1_wmma_k<<<(N + 15) / 16, 128>>>(N);
    gather1_k<<<(N * 32 + T - 1) / T, T>>>(b1, N);

    // layer 2
    gemm2_k<<<(N + T - 1) / T, T>>>(W2, N);
    gather2_k<<<(N * 32 + T - 1) / T, T>>>(out, b2, N);
}

// round 13
// speedup vs baseline: 1.0825x; 1.0372x over previous
#include <cuda_runtime.h>
#include <cuda_fp16.h>
#include <mma.h>

using namespace nvcuda;

#define MAXN 100000
#define MAXE 1600000
#define CAP  64

typedef unsigned long long ull;

// ---- scratch (device globals; no allocation allowed) ----
__device__ int    g_cnt[MAXN];                    // in-degree (excl. self loop)
__device__ float  g_dinv[MAXN];
__device__ int    g_bkt[(size_t)MAXN * CAP];      // per-dst src indices (25.6MB)
__device__ float  g_bw [(size_t)MAXN * CAP];      // per-dst edge weights (25.6MB)
__device__ __half g_wh[128 * 64];                 // fp16 copy of W1
__device__ float  g_h1[(size_t)(MAXN + 64) * 64]; // X@W1 (fp32; +64 rows pad for last tile)
__device__ float  g_h2[(size_t)MAXN * 64];        // relu layer-1 output
__device__ float  g_h3[(size_t)MAXN * 40];        // h2@W2

// packed f32x2 FMA: d = a*b + d
#define FMA2(d, a, b) asm("fma.rn.f32x2 %0, %1, %2, %0;" : "+l"(d) : "l"(a), "l"(b))
#define PACK2(out, lo, hi) asm("mov.b64 %0, {%1, %2};" : "=l"(out) : "f"(lo), "f"(hi))

// ---------------- bucket build ----------------
__global__ void bucket_k(const int* __restrict__ ei, int E, int N) {
    int i = blockIdx.x * blockDim.x + threadIdx.x;
    if (i >= E) return;
    int s = ei[i];
    int d = ei[E + i];
    if ((unsigned)s >= (unsigned)N || (unsigned)d >= (unsigned)N) return;
    int pos = atomicAdd(g_cnt + d, 1);
    if (pos < CAP) g_bkt[(size_t)d * CAP + pos] = s;
}

__global__ void dinv_k(int N) {
    int i = blockIdx.x * blockDim.x + threadIdx.x;
    if (i < N) g_dinv[i] = rsqrtf((float)g_cnt[i] + 1.0f);  // +1 self loop
}

// per-slot edge weight: w = dinv[src]*dinv[dst]; one warp per node
__global__ void fillw_k(int N) {
    int wid = (blockIdx.x * blockDim.x + threadIdx.x) >> 5;
    int lane = threadIdx.x & 31;
    if (wid >= N) return;
    int deg = min(g_cnt[wid], CAP);
    float dn = g_dinv[wid];
    const int* bp = g_bkt + (size_t)wid * CAP;
    float* wp = g_bw + (size_t)wid * CAP;
    for (int j = lane; j < deg; j += 32)
        wp[j] = __ldg(g_dinv + bp[j]) * dn;
}

__global__ void cvtW_k(const float* __restrict__ W) {
    for (int i = threadIdx.x; i < 128 * 64; i += blockDim.x)
        g_wh[i] = __float2half(W[i]);
}

// ---------------- GEMM layer 1 via HMMA: g_h1 = fp16(X) @ fp16(W1) ----------
// block = 128 threads / 4 warps; 64 rows x 64 cols per block.
// X tile converted fp32->fp16 into smem on the fly (X read exactly once).
// Warp w owns rows [w*16, w*16+16) x all 64 cols (4 accumulator frags).
__global__ __launch_bounds__(128) void gemm1_wmma_k(const float* __restrict__ X, int N)
{
    __shared__ __align__(16) __half Xs[64 * 128];   // 16KB
    __shared__ __align__(16) __half Wsh[128 * 64];  // 16KB

    int tid = threadIdx.x;
    int warp = tid >> 5;
    int R = blockIdx.x * 64;                        // first row of this tile

    // stage W1 (fp16 global, L2-hot) -> smem, 16KB as uint4
    {
        const uint4* src = (const uint4*)g_wh;
        uint4* dst = (uint4*)Wsh;
        for (int i = tid; i < 128 * 64 * 2 / 16; i += 128) dst[i] = src[i];
    }
    // stage X tile: 64 rows x 128 cols fp32 -> fp16 smem (zero-pad past N)
    for (int idx = tid; idx < 64 * 32; idx += 128) {
        int row = idx >> 5;            // 0..63
        int c4 = idx & 31;             // float4 index within row
        int gr = R + row;
        float4 v = (gr < N) ? ((const float4*)X)[(size_t)gr * 32 + c4]
                            : make_float4(0.f, 0.f, 0.f, 0.f);
        __half2* dp = (__half2*)(Xs + row * 128 + c4 * 4);
        dp[0] = __floats2half2_rn(v.x, v.y);
        dp[1] = __floats2half2_rn(v.z, v.w);
    }
    __syncthreads();

    wmma::fragment<wmma::matrix_a, 16, 16, 16, __half, wmma::row_major> a;
    wmma::fragment<wmma::matrix_b, 16, 16, 16, __half, wmma::row_major> b;
    wmma::fragment<wmma::accumulator, 16, 16, 16, float> c[4];
#pragma unroll
    for (int t = 0; t < 4; t++) wmma::fill_fragment(c[t], 0.0f);

    const __half* xbase = Xs + warp * 16 * 128;
#pragma unroll
    for (int k = 0; k < 8; k++) {
        wmma::load_matrix_sync(a, xbase + k * 16, 128);
#pragma unroll
        for (int t = 0; t < 4; t++) {
            wmma::load_matrix_sync(b, Wsh + k * 16 * 64 + t * 16, 64);
            wmma::mma_sync(c[t], a, b, c[t]);
        }
    }

    float* obase = g_h1 + (size_t)(R + warp * 16) * 64;   // pad rows absorb overflow
#pragma unroll
    for (int t = 0; t < 4; t++)
        wmma::store_matrix_sync(obase + t * 16, c[t], 64, wmma::mem_row_major);
}

// -------- gather layer 1: h2 = relu( sum_in h1[s]*w + h1[n]*dinv^2 + b1 )
__global__ __launch_bounds__(256) void gather1_k(const float* __restrict__ b1, int N)
{
    int wid = (blockIdx.x * 256 + threadIdx.x) >> 5;
    int lane = threadIdx.x & 31;
    if (wid >= N) return;
    int n = wid;
    int half = lane >> 4;
    int hl = lane & 15;

    int deg = min(g_cnt[n], CAP);
    const int* bp = g_bkt + (size_t)n * CAP;
    const float* wp = g_bw + (size_t)n * CAP;

    float4 acc = make_float4(0.f, 0.f, 0.f, 0.f);
    int e = 0;
    for (; e + 7 < deg; e += 8) {
        int off = e + half * 4;
        int4   ss = *(const int4*)(bp + off);
        float4 ww = *(const float4*)(wp + off);
        float4 v0 = *(const float4*)(g_h1 + (size_t)ss.x * 64 + hl * 4);
        float4 v1 = *(const float4*)(g_h1 + (size_t)ss.y * 64 + hl * 4);
        float4 v2 = *(const float4*)(g_h1 + (size_t)ss.z * 64 + hl * 4);
        float4 v3 = *(const float4*)(g_h1 + (size_t)ss.w * 64 + hl * 4);
        acc.x += v0.x * ww.x + v1.x * ww.y + v2.x * ww.z + v3.x * ww.w;
        acc.y += v0.y * ww.x + v1.y * ww.y + v2.y * ww.z + v3.y * ww.w;
        acc.z += v0.z * ww.x + v1.z * ww.y + v2.z * ww.z + v3.z * ww.w;
        acc.w += v0.w * ww.x + v1.w * ww.y + v2.w * ww.z + v3.w * ww.w;
    }
    for (int r = e + half; r < deg; r += 2) {
        int s0 = __ldg(bp + r);
        float w0 = __ldg(wp + r);
        float4 v0 = *(const float4*)(g_h1 + (size_t)s0 * 64 + hl * 4);
        acc.x += v0.x * w0; acc.y += v0.y * w0;
        acc.z += v0.z * w0; acc.w += v0.w * w0;
    }

    acc.x += __shfl_xor_sync(0xFFFFFFFFu, acc.x, 16);
    acc.y += __shfl_xor_sync(0xFFFFFFFFu, acc.y, 16);
    acc.z += __shfl_xor_sync(0xFFFFFFFFu, acc.z, 16);
    acc.w += __shfl_xor_sync(0xFFFFFFFFu, acc.w, 16);

    if (half == 0) {
        float dn = g_dinv[n];
        float sl = dn * dn;
        float4 h = *(const float4*)(g_h1 + (size_t)n * 64 + hl * 4);
        float4 bb = *(const float4*)(b1 + hl * 4);
        float4 o;
        o.x = fmaxf(acc.x + h.x * sl + bb.x, 0.f);
        o.y = fmaxf(acc.y + h.y * sl + bb.y, 0.f);
        o.z = fmaxf(acc.z + h.z * sl + bb.z, 0.f);
        o.w = fmaxf(acc.w + h.w * sl + bb.w, 0.f);
        *(float4*)(g_h2 + (size_t)n * 64 + hl * 4) = o;
    }
}

// ---------------- GEMM layer 2: g_h3 = h2 @ W2 (f32x2 packed) ----------------
__global__ __launch_bounds__(256) void gemm2_k(const float* __restrict__ W, int N)
{
    __shared__ __align__(16) float Ws[64 * 40];
    for (int i = threadIdx.x; i < 64 * 40; i += 256) Ws[i] = W[i];
    __syncthreads();

    int r = blockIdx.x * 256 + threadIdx.x;
    if (r >= N) return;

    ull acc[20];
#pragma unroll
    for (int j = 0; j < 20; j++) acc[j] = 0ULL;

    const float4* xr = (const float4*)(g_h2 + (size_t)r * 64);
#pragma unroll 1
    for (int k4 = 0; k4 < 16; k4++) {
        float4 xv = xr[k4];
        ull xa, xb, xc, xd;
        PACK2(xa, xv.x, xv.x); PACK2(xb, xv.y, xv.y);
        PACK2(xc, xv.z, xv.z); PACK2(xd, xv.w, xv.w);
        const ulonglong2* w0 = (const ulonglong2*)(Ws + (k4 * 4 + 0) * 40);
        const ulonglong2* w1 = (const ulonglong2*)(Ws + (k4 * 4 + 1) * 40);
        const ulonglong2* w2 = (const ulonglong2*)(Ws + (k4 * 4 + 2) * 40);
        const ulonglong2* w3 = (const ulonglong2*)(Ws + (k4 * 4 + 3) * 40);
#pragma unroll
        for (int j = 0; j < 10; j++) {
            ulonglong2 a0 = w0[j]; FMA2(acc[2*j], xa, a0.x); FMA2(acc[2*j+1], xa, a0.y);
            ulonglong2 a1 = w1[j]; FMA2(acc[2*j], xb, a1.x); FMA2(acc[2*j+1], xb, a1.y);
            ulonglong2 a2 = w2[j]; FMA2(acc[2*j], xc, a2.x); FMA2(acc[2*j+1], xc, a2.y);
            ulonglong2 a3 = w3[j]; FMA2(acc[2*j], xd, a3.x); FMA2(acc[2*j+1], xd, a3.y);
        }
    }

    ulonglong2* Hp = (ulonglong2*)(g_h3 + (size_t)r * 40);
#pragma unroll
    for (int j = 0; j < 10; j++) {
        ulonglong2 v; v.x = acc[2*j]; v.y = acc[2*j+1];
        Hp[j] = v;
    }
}

// -------- gather layer 2 + bias + log_softmax --------
__global__ __launch_bounds__(256) void gather2_k(float* __restrict__ out,
                                                 const float* __restrict__ b2, int N)
{
    int wid = (blockIdx.x * 256 + threadIdx.x) >> 5;
    int lane = threadIdx.x & 31;
    if (wid >= N) return;
    int n = wid;
    bool act = lane < 20;
    int fo = act ? lane * 2 : 0;

    int deg = min(g_cnt[n], CAP);
    const int* bp = g_bkt + (size_t)n * CAP;
    const float* wp = g_bw + (size_t)n * CAP;

    float2 a0 = make_float2(0.f, 0.f), a1 = make_float2(0.f, 0.f);
    float2 a2 = make_float2(0.f, 0.f), a3 = make_float2(0.f, 0.f);
    int e = 0;
    for (; e + 3 < deg; e += 4) {
        int4   ss = *(const int4*)(bp + e);
        float4 ww = *(const float4*)(wp + e);
        float2 v0 = *(const float2*)(g_h3 + (size_t)ss.x * 40 + fo);
        float2 v1 = *(const float2*)(g_h3 + (size_t)ss.y * 40 + fo);
        float2 v2 = *(const float2*)(g_h3 + (size_t)ss.z * 40 + fo);
        float2 v3 = *(const float2*)(g_h3 + (size_t)ss.w * 40 + fo);
        a0.x += v0.x * ww.x; a0.y += v0.y * ww.x;
        a1.x += v1.x * ww.y; a1.y += v1.y * ww.y;
        a2.x += v2.x * ww.z; a2.y += v2.y * ww.z;
        a3.x += v3.x * ww.w; a3.y += v3.y * ww.w;
    }
    for (; e < deg; e++) {
        int s0 = __ldg(bp + e);
        float w0 = __ldg(wp + e);
        float2 v0 = *(const float2*)(g_h3 + (size_t)s0 * 40 + fo);
        a0.x += v0.x * w0; a0.y += v0.y * w0;
    }

    float dn = g_dinv[n];
    float sl = dn * dn;
    float2 h = *(const float2*)(g_h3 + (size_t)n * 40 + fo);
    float2 bb = *(const float2*)(b2 + fo);
    float vx = a0.x + a1.x + a2.x + a3.x + h.x * sl + bb.x;
    float vy = a0.y + a1.y + a2.y + a3.y + h.y * sl + bb.y;

    float m = act ? fmaxf(vx, vy) : -3.0e38f;
#pragma unroll
    for (int o = 16; o > 0; o >>= 1) m = fmaxf(m, __shfl_xor_sync(0xFFFFFFFFu, m, o));
    float s = act ? (expf(vx - m) + expf(vy - m)) : 0.f;
#pragma unroll
    for (int o = 16; o > 0; o >>= 1) s += __shfl_xor_sync(0xFFFFFFFFu, s, o);
    float lse = m + logf(s);

    if (act)
        *(float2*)(out + (size_t)n * 40 + fo) = make_float2(vx - lse, vy - lse);
}

extern "C" void kernel_launch(void* const* d_in, const int* in_sizes, int n_in,
                              void* d_out, int out_size)
{
    const float* x  = (const float*)d_in[0];
    const int*   ei = (const int*)d_in[1];      // int32 (JAX x64 disabled)
    const float* W1 = (const float*)d_in[2];
    const float* b1 = (const float*)d_in[3];
    const float* W2 = (const float*)d_in[4];
    const float* b2 = (const float*)d_in[5];
    float* out = (float*)d_out;

    int N = in_sizes[0] / 128;
    int E = in_sizes[1] / 2;
    const int T = 256;

    // setup
    void* cnt_ptr = 0;
    cudaGetSymbolAddress(&cnt_ptr, g_cnt);
    cudaMemsetAsync(cnt_ptr, 0, (size_t)N * sizeof(int));
    cvtW_k<<<1, 256>>>(W1);
    bucket_k<<<(E + T - 1) / T, T>>>(ei, E, N);
    dinv_k<<<(N + T - 1) / T, T>>>(N);
    fillw_k<<<(N * 32 + T - 1) / T, T>>>(N);

    // layer 1: fused-convert HMMA GEMM + gather
    gemm1_wmma_k<<<(N + 63) / 64, 128>>>(x, N);
    gather1_k<<<(N * 32 + T - 1) / T, T>>>(b1, N);

    // layer 2
    gemm2_k<<<(N + T - 1) / T, T>>>(W2, N);
    gather2_k<<<(N * 32 + T - 1) / T, T>>>(out, b2, N);
}

// round 16
// speedup vs baseline: 1.2569x; 1.1611x over previous
#include <cuda_runtime.h>
#include <cuda_fp16.h>
#include <mma.h>

using namespace nvcuda;

#define MAXN 100000
#define MAXE 1600000
#define CAP  64

typedef unsigned long long ull;

// ---- scratch (device globals; no allocation allowed) ----
__device__ int    g_cnt[MAXN];                    // in-degree (excl. self loop)
__device__ float  g_dinv[MAXN];
__device__ int    g_bkt[(size_t)MAXN * CAP];      // per-dst src indices (25.6MB)
__device__ __half g_wh[128 * 64];                 // fp16 copy of W1
__device__ float  g_h1[(size_t)(MAXN + 64) * 64]; // dinv*(X@W1) (fp32; +64 rows pad)
__device__ float  g_h2[(size_t)MAXN * 64];        // relu layer-1 output
__device__ float  g_h3[(size_t)MAXN * 40];        // dinv*(h2@W2)

// packed f32x2 ops
#define FMA2(d, a, b) asm("fma.rn.f32x2 %0, %1, %2, %0;" : "+l"(d) : "l"(a), "l"(b))
#define MUL2(d, a)    asm("mul.rn.f32x2 %0, %0, %1;" : "+l"(d) : "l"(a))
#define PACK2(out, lo, hi) asm("mov.b64 %0, {%1, %2};" : "=l"(out) : "f"(lo), "f"(hi))

// ---------------- bucket build ----------------
__global__ void bucket_k(const int* __restrict__ ei, int E, int N) {
    int i = blockIdx.x * blockDim.x + threadIdx.x;
    if (i >= E) return;
    int s = ei[i];
    int d = ei[E + i];
    if ((unsigned)s >= (unsigned)N || (unsigned)d >= (unsigned)N) return;
    int pos = atomicAdd(g_cnt + d, 1);
    if (pos < CAP) g_bkt[(size_t)d * CAP + pos] = s;
}

__global__ void dinv_k(int N) {
    int i = blockIdx.x * blockDim.x + threadIdx.x;
    if (i < N) g_dinv[i] = rsqrtf((float)g_cnt[i] + 1.0f);  // +1 self loop
}

__global__ void cvtW_k(const float* __restrict__ W) {
    for (int i = threadIdx.x; i < 128 * 64; i += blockDim.x)
        g_wh[i] = __float2half(W[i]);
}

// ---------------- GEMM layer 1 via HMMA: g_h1 = (dinv*X)fp16 @ fp16(W1) -----
// block = 128 threads / 4 warps; 64 rows x 64 cols per block.
// X row scaled by dinv[row] during fp32->fp16 smem staging (free).
__global__ __launch_bounds__(128) void gemm1_wmma_k(const float* __restrict__ X, int N)
{
    __shared__ __align__(16) __half Xs[64 * 128];   // 16KB
    __shared__ __align__(16) __half Wsh[128 * 64];  // 16KB

    int tid = threadIdx.x;
    int warp = tid >> 5;
    int R = blockIdx.x * 64;

    {
        const uint4* src = (const uint4*)g_wh;
        uint4* dst = (uint4*)Wsh;
        for (int i = tid; i < 128 * 64 * 2 / 16; i += 128) dst[i] = src[i];
    }
    for (int idx = tid; idx < 64 * 32; idx += 128) {
        int row = idx >> 5;
        int c4 = idx & 31;
        int gr = R + row;
        float4 v = (gr < N) ? ((const float4*)X)[(size_t)gr * 32 + c4]
                            : make_float4(0.f, 0.f, 0.f, 0.f);
        float dnr = (gr < N) ? g_dinv[gr] : 0.f;
        __half2* dp = (__half2*)(Xs + row * 128 + c4 * 4);
        dp[0] = __floats2half2_rn(v.x * dnr, v.y * dnr);
        dp[1] = __floats2half2_rn(v.z * dnr, v.w * dnr);
    }
    __syncthreads();

    wmma::fragment<wmma::matrix_a, 16, 16, 16, __half, wmma::row_major> a;
    wmma::fragment<wmma::matrix_b, 16, 16, 16, __half, wmma::row_major> b;
    wmma::fragment<wmma::accumulator, 16, 16, 16, float> c[4];
#pragma unroll
    for (int t = 0; t < 4; t++) wmma::fill_fragment(c[t], 0.0f);

    const __half* xbase = Xs + warp * 16 * 128;
#pragma unroll
    for (int k = 0; k < 8; k++) {
        wmma::load_matrix_sync(a, xbase + k * 16, 128);
#pragma unroll
        for (int t = 0; t < 4; t++) {
            wmma::load_matrix_sync(b, Wsh + k * 16 * 64 + t * 16, 64);
            wmma::mma_sync(c[t], a, b, c[t]);
        }
    }

    float* obase = g_h1 + (size_t)(R + warp * 16) * 64;
#pragma unroll
    for (int t = 0; t < 4; t++)
        wmma::store_matrix_sync(obase + t * 16, c[t], 64, wmma::mem_row_major);
}

// -------- gather layer 1: h2 = relu( dinv[n]*( sum_in h1'[s] + h1'[n] ) + b1 )
// pure unweighted sum — no per-edge weights
__global__ __launch_bounds__(256) void gather1_k(const float* __restrict__ b1, int N)
{
    int wid = (blockIdx.x * 256 + threadIdx.x) >> 5;
    int lane = threadIdx.x & 31;
    if (wid >= N) return;
    int n = wid;
    int half = lane >> 4;
    int hl = lane & 15;

    int deg = min(g_cnt[n], CAP);
    const int* bp = g_bkt + (size_t)n * CAP;

    float4 acc = make_float4(0.f, 0.f, 0.f, 0.f);
    int e = 0;
    for (; e + 7 < deg; e += 8) {
        int4 ss = *(const int4*)(bp + e + half * 4);
        float4 v0 = *(const float4*)(g_h1 + (size_t)ss.x * 64 + hl * 4);
        float4 v1 = *(const float4*)(g_h1 + (size_t)ss.y * 64 + hl * 4);
        float4 v2 = *(const float4*)(g_h1 + (size_t)ss.z * 64 + hl * 4);
        float4 v3 = *(const float4*)(g_h1 + (size_t)ss.w * 64 + hl * 4);
        acc.x += (v0.x + v1.x) + (v2.x + v3.x);
        acc.y += (v0.y + v1.y) + (v2.y + v3.y);
        acc.z += (v0.z + v1.z) + (v2.z + v3.z);
        acc.w += (v0.w + v1.w) + (v2.w + v3.w);
    }
    for (int r = e + half; r < deg; r += 2) {
        int s0 = __ldg(bp + r);
        float4 v0 = *(const float4*)(g_h1 + (size_t)s0 * 64 + hl * 4);
        acc.x += v0.x; acc.y += v0.y; acc.z += v0.z; acc.w += v0.w;
    }

    acc.x += __shfl_xor_sync(0xFFFFFFFFu, acc.x, 16);
    acc.y += __shfl_xor_sync(0xFFFFFFFFu, acc.y, 16);
    acc.z += __shfl_xor_sync(0xFFFFFFFFu, acc.z, 16);
    acc.w += __shfl_xor_sync(0xFFFFFFFFu, acc.w, 16);

    if (half == 0) {
        float dn = g_dinv[n];
        float4 h = *(const float4*)(g_h1 + (size_t)n * 64 + hl * 4);
        float4 bb = *(const float4*)(b1 + hl * 4);
        float4 o;
        o.x = fmaxf(dn * (acc.x + h.x) + bb.x, 0.f);
        o.y = fmaxf(dn * (acc.y + h.y) + bb.y, 0.f);
        o.z = fmaxf(dn * (acc.z + h.z) + bb.z, 0.f);
        o.w = fmaxf(dn * (acc.w + h.w) + bb.w, 0.f);
        *(float4*)(g_h2 + (size_t)n * 64 + hl * 4) = o;
    }
}

// ---------------- GEMM layer 2: g_h3 = dinv[r] * (h2 @ W2) ------------------
__global__ __launch_bounds__(256) void gemm2_k(const float* __restrict__ W, int N)
{
    __shared__ __align__(16) float Ws[64 * 40];
    for (int i = threadIdx.x; i < 64 * 40; i += 256) Ws[i] = W[i];
    __syncthreads();

    int r = blockIdx.x * 256 + threadIdx.x;
    if (r >= N) return;

    ull acc[20];
#pragma unroll
    for (int j = 0; j < 20; j++) acc[j] = 0ULL;

    const float4* xr = (const float4*)(g_h2 + (size_t)r * 64);
#pragma unroll 1
    for (int k4 = 0; k4 < 16; k4++) {
        float4 xv = xr[k4];
        ull xa, xb, xc, xd;
        PACK2(xa, xv.x, xv.x); PACK2(xb, xv.y, xv.y);
        PACK2(xc, xv.z, xv.z); PACK2(xd, xv.w, xv.w);
        const ulonglong2* w0 = (const ulonglong2*)(Ws + (k4 * 4 + 0) * 40);
        const ulonglong2* w1 = (const ulonglong2*)(Ws + (k4 * 4 + 1) * 40);
        const ulonglong2* w2 = (const ulonglong2*)(Ws + (k4 * 4 + 2) * 40);
        const ulonglong2* w3 = (const ulonglong2*)(Ws + (k4 * 4 + 3) * 40);
#pragma unroll
        for (int j = 0; j < 10; j++) {
            ulonglong2 a0 = w0[j]; FMA2(acc[2*j], xa, a0.x); FMA2(acc[2*j+1], xa, a0.y);
            ulonglong2 a1 = w1[j]; FMA2(acc[2*j], xb, a1.x); FMA2(acc[2*j+1], xb, a1.y);
            ulonglong2 a2 = w2[j]; FMA2(acc[2*j], xc, a2.x); FMA2(acc[2*j+1], xc, a2.y);
            ulonglong2 a3 = w3[j]; FMA2(acc[2*j], xd, a3.x); FMA2(acc[2*j+1], xd, a3.y);
        }
    }

    // epilogue: scale by dinv[r]
    float dn = g_dinv[r];
    ull dn2; PACK2(dn2, dn, dn);
#pragma unroll
    for (int j = 0; j < 20; j++) MUL2(acc[j], dn2);

    ulonglong2* Hp = (ulonglong2*)(g_h3 + (size_t)r * 40);
#pragma unroll
    for (int j = 0; j < 10; j++) {
        ulonglong2 v; v.x = acc[2*j]; v.y = acc[2*j+1];
        Hp[j] = v;
    }
}

// -------- gather layer 2 + bias + log_softmax --------
// vx,vy = dinv[n]*( sum_in h3'[s] + h3'[n] ) + b2 ; then warp log-softmax
__global__ __launch_bounds__(256) void gather2_k(float* __restrict__ out,
                                                 const float* __restrict__ b2, int N)
{
    int wid = (blockIdx.x * 256 + threadIdx.x) >> 5;
    int lane = threadIdx.x & 31;
    if (wid >= N) return;
    int n = wid;
    bool act = lane < 20;
    int fo = act ? lane * 2 : 0;

    int deg = min(g_cnt[n], CAP);
    const int* bp = g_bkt + (size_t)n * CAP;

    float2 a0 = make_float2(0.f, 0.f), a1 = make_float2(0.f, 0.f);
    float2 a2 = make_float2(0.f, 0.f), a3 = make_float2(0.f, 0.f);
    int e = 0;
    for (; e + 3 < deg; e += 4) {
        int4 ss = *(const int4*)(bp + e);
        float2 v0 = *(const float2*)(g_h3 + (size_t)ss.x * 40 + fo);
        float2 v1 = *(const float2*)(g_h3 + (size_t)ss.y * 40 + fo);
        float2 v2 = *(const float2*)(g_h3 + (size_t)ss.z * 40 + fo);
        float2 v3 = *(const float2*)(g_h3 + (size_t)ss.w * 40 + fo);
        a0.x += v0.x; a0.y += v0.y;
        a1.x += v1.x; a1.y += v1.y;
        a2.x += v2.x; a2.y += v2.y;
        a3.x += v3.x; a3.y += v3.y;
    }
    for (; e < deg; e++) {
        int s0 = __ldg(bp + e);
        float2 v0 = *(const float2*)(g_h3 + (size_t)s0 * 40 + fo);
        a0.x += v0.x; a0.y += v0.y;
    }

    float dn = g_dinv[n];
    float2 h = *(const float2*)(g_h3 + (size_t)n * 40 + fo);
    float2 bb = *(const float2*)(b2 + fo);
    float vx = dn * ((a0.x + a1.x) + (a2.x + a3.x) + h.x) + bb.x;
    float vy = dn * ((a0.y + a1.y) + (a2.y + a3.y) + h.y) + bb.y;

    float m = act ? fmaxf(vx, vy) : -3.0e38f;
#pragma unroll
    for (int o = 16; o > 0; o >>= 1) m = fmaxf(m, __shfl_xor_sync(0xFFFFFFFFu, m, o));
    float s = act ? (expf(vx - m) + expf(vy - m)) : 0.f;
#pragma unroll
    for (int o = 16; o > 0; o >>= 1) s += __shfl_xor_sync(0xFFFFFFFFu, s, o);
    float lse = m + logf(s);

    if (act)
        *(float2*)(out + (size_t)n * 40 + fo) = make_float2(vx - lse, vy - lse);
}

extern "C" void kernel_launch(void* const* d_in, const int* in_sizes, int n_in,
                              void* d_out, int out_size)
{
    const float* x  = (const float*)d_in[0];
    const int*   ei = (const int*)d_in[1];      // int32 (JAX x64 disabled)
    const float* W1 = (const float*)d_in[2];
    const float* b1 = (const float*)d_in[3];
    const float* W2 = (const float*)d_in[4];
    const float* b2 = (const float*)d_in[5];
    float* out = (float*)d_out;

    int N = in_sizes[0] / 128;
    int E = in_sizes[1] / 2;
    const int T = 256;

    // setup
    void* cnt_ptr = 0;
    cudaGetSymbolAddress(&cnt_ptr, g_cnt);
    cudaMemsetAsync(cnt_ptr, 0, (size_t)N * sizeof(int));
    cvtW_k<<<1, 256>>>(W1);
    bucket_k<<<(E + T - 1) / T, T>>>(ei, E, N);
    dinv_k<<<(N + T - 1) / T, T>>>(N);

    // layer 1: fused-scale HMMA GEMM + unweighted gather
    gemm1_wmma_k<<<(N + 63) / 64, 128>>>(x, N);
    gather1_k<<<(N * 32 + T - 1) / T, T>>>(b1, N);

    // layer 2
    gemm2_k<<<(N + T - 1) / T, T>>>(W2, N);
    gather2_k<<<(N * 32 + T - 1) / T, T>>>(out, b2, N);
}

// round 17
// speedup vs baseline: 1.3248x; 1.0540x over previous
#include <cuda_runtime.h>
#include <cuda_fp16.h>
#include <mma.h>

using namespace nvcuda;

#define MAXN 100000
#define MAXE 1600000
#define CAP  64

typedef unsigned long long ull;

// ---- scratch (device globals; no allocation allowed) ----
__device__ int    g_cnt[MAXN];                    // in-degree (excl. self loop)
__device__ float  g_dinv[MAXN];
__device__ int    g_bkt[(size_t)MAXN * CAP];      // per-dst src indices (25.6MB)
__device__ __half g_wh[128 * 64];                 // fp16 copy of W1
__device__ float  g_h1[(size_t)(MAXN + 64) * 64]; // dinv*(X@W1) (fp32; +64 rows pad)
__device__ float  g_h2[(size_t)MAXN * 64];        // relu layer-1 output
__device__ float  g_h3[(size_t)MAXN * 40];        // dinv*(h2@W2)

// packed f32x2 ops
#define FMA2(d, a, b) asm("fma.rn.f32x2 %0, %1, %2, %0;" : "+l"(d) : "l"(a), "l"(b))
#define MUL2(d, a)    asm("mul.rn.f32x2 %0, %0, %1;" : "+l"(d) : "l"(a))
#define PACK2(out, lo, hi) asm("mov.b64 %0, {%1, %2};" : "=l"(out) : "f"(lo), "f"(hi))

// ---------------- bucket build ----------------
__global__ void bucket_k(const int* __restrict__ ei, int E, int N) {
    int i = blockIdx.x * blockDim.x + threadIdx.x;
    if (i >= E) return;
    int s = ei[i];
    int d = ei[E + i];
    if ((unsigned)s >= (unsigned)N || (unsigned)d >= (unsigned)N) return;
    int pos = atomicAdd(g_cnt + d, 1);
    if (pos < CAP) g_bkt[(size_t)d * CAP + pos] = s;
}

__global__ void dinv_k(int N) {
    int i = blockIdx.x * blockDim.x + threadIdx.x;
    if (i < N) g_dinv[i] = rsqrtf((float)g_cnt[i] + 1.0f);  // +1 self loop
}

__global__ void cvtW_k(const float* __restrict__ W) {
    for (int i = threadIdx.x; i < 128 * 64; i += blockDim.x)
        g_wh[i] = __float2half(W[i]);
}

// ---------------- GEMM layer 1 via HMMA: g_h1 = (dinv*X)fp16 @ fp16(W1) -----
// Per-warp independent tiles: warp owns 16 rows x 64 cols. No block barrier.
// X slab staged fp32->fp16 (scaled by dinv) into a private 4KB smem slab;
// B fragments loaded directly from g_wh (global, L1-hot).
__global__ __launch_bounds__(256) void gemm1_wmma_k(const float* __restrict__ X, int N)
{
    __shared__ __align__(16) __half Xs[8][16 * 128];  // 4KB per warp, 32KB total

    int warp = threadIdx.x >> 5;
    int lane = threadIdx.x & 31;
    size_t R = ((size_t)blockIdx.x * 8 + warp) * 16;  // first row of warp tile
    if (R >= (size_t)N) return;

    __half* xs = Xs[warp];
    // stage 16 rows x 128 cols: 512 float4s, 16 per lane, issued back-to-back
#pragma unroll
    for (int i = 0; i < 16; i++) {
        int idx = lane + i * 32;          // 0..511
        int row = idx >> 5;
        int c4 = idx & 31;
        size_t gr = R + row;
        float4 v = (gr < (size_t)N) ? ((const float4*)X)[gr * 32 + c4]
                                    : make_float4(0.f, 0.f, 0.f, 0.f);
        float dnr = (gr < (size_t)N) ? g_dinv[gr] : 0.f;
        __half2* dp = (__half2*)(xs + row * 128 + c4 * 4);
        dp[0] = __floats2half2_rn(v.x * dnr, v.y * dnr);
        dp[1] = __floats2half2_rn(v.z * dnr, v.w * dnr);
    }
    __syncwarp();

    wmma::fragment<wmma::matrix_a, 16, 16, 16, __half, wmma::row_major> a;
    wmma::fragment<wmma::matrix_b, 16, 16, 16, __half, wmma::row_major> b;
    wmma::fragment<wmma::accumulator, 16, 16, 16, float> c[4];
#pragma unroll
    for (int t = 0; t < 4; t++) wmma::fill_fragment(c[t], 0.0f);

#pragma unroll
    for (int k = 0; k < 8; k++) {
        wmma::load_matrix_sync(a, xs + k * 16, 128);
#pragma unroll
        for (int t = 0; t < 4; t++) {
            wmma::load_matrix_sync(b, g_wh + k * 16 * 64 + t * 16, 64);
            wmma::mma_sync(c[t], a, b, c[t]);
        }
    }

    float* obase = g_h1 + R * 64;   // +64-row pad absorbs last partial tile
#pragma unroll
    for (int t = 0; t < 4; t++)
        wmma::store_matrix_sync(obase + t * 16, c[t], 64, wmma::mem_row_major);
}

// -------- gather layer 1: h2 = relu( dinv[n]*( sum_in h1'[s] + h1'[n] ) + b1 )
__global__ __launch_bounds__(256) void gather1_k(const float* __restrict__ b1, int N)
{
    int wid = (blockIdx.x * 256 + threadIdx.x) >> 5;
    int lane = threadIdx.x & 31;
    if (wid >= N) return;
    int n = wid;
    int half = lane >> 4;
    int hl = lane & 15;

    int deg = min(g_cnt[n], CAP);
    const int* bp = g_bkt + (size_t)n * CAP;

    float4 acc = make_float4(0.f, 0.f, 0.f, 0.f);
    int e = 0;
    for (; e + 7 < deg; e += 8) {
        int4 ss = *(const int4*)(bp + e + half * 4);
        float4 v0 = *(const float4*)(g_h1 + (size_t)ss.x * 64 + hl * 4);
        float4 v1 = *(const float4*)(g_h1 + (size_t)ss.y * 64 + hl * 4);
        float4 v2 = *(const float4*)(g_h1 + (size_t)ss.z * 64 + hl * 4);
        float4 v3 = *(const float4*)(g_h1 + (size_t)ss.w * 64 + hl * 4);
        acc.x += (v0.x + v1.x) + (v2.x + v3.x);
        acc.y += (v0.y + v1.y) + (v2.y + v3.y);
        acc.z += (v0.z + v1.z) + (v2.z + v3.z);
        acc.w += (v0.w + v1.w) + (v2.w + v3.w);
    }
    for (int r = e + half; r < deg; r += 2) {
        int s0 = __ldg(bp + r);
        float4 v0 = *(const float4*)(g_h1 + (size_t)s0 * 64 + hl * 4);
        acc.x += v0.x; acc.y += v0.y; acc.z += v0.z; acc.w += v0.w;
    }

    acc.x += __shfl_xor_sync(0xFFFFFFFFu, acc.x, 16);
    acc.y += __shfl_xor_sync(0xFFFFFFFFu, acc.y, 16);
    acc.z += __shfl_xor_sync(0xFFFFFFFFu, acc.z, 16);
    acc.w += __shfl_xor_sync(0xFFFFFFFFu, acc.w, 16);

    if (half == 0) {
        float dn = g_dinv[n];
        float4 h = *(const float4*)(g_h1 + (size_t)n * 64 + hl * 4);
        float4 bb = *(const float4*)(b1 + hl * 4);
        float4 o;
        o.x = fmaxf(dn * (acc.x + h.x) + bb.x, 0.f);
        o.y = fmaxf(dn * (acc.y + h.y) + bb.y, 0.f);
        o.z = fmaxf(dn * (acc.z + h.z) + bb.z, 0.f);
        o.w = fmaxf(dn * (acc.w + h.w) + bb.w, 0.f);
        *(float4*)(g_h2 + (size_t)n * 64 + hl * 4) = o;
    }
}

// ---------------- GEMM layer 2: g_h3 = dinv[r] * (h2 @ W2) ------------------
__global__ __launch_bounds__(256) void gemm2_k(const float* __restrict__ W, int N)
{
    __shared__ __align__(16) float Ws[64 * 40];
    for (int i = threadIdx.x; i < 64 * 40; i += 256) Ws[i] = W[i];
    __syncthreads();

    int r = blockIdx.x * 256 + threadIdx.x;
    if (r >= N) return;

    ull acc[20];
#pragma unroll
    for (int j = 0; j < 20; j++) acc[j] = 0ULL;

    const float4* xr = (const float4*)(g_h2 + (size_t)r * 64);
#pragma unroll 1
    for (int k4 = 0; k4 < 16; k4++) {
        float4 xv = xr[k4];
        ull xa, xb, xc, xd;
        PACK2(xa, xv.x, xv.x); PACK2(xb, xv.y, xv.y);
        PACK2(xc, xv.z, xv.z); PACK2(xd, xv.w, xv.w);
        const ulonglong2* w0 = (const ulonglong2*)(Ws + (k4 * 4 + 0) * 40);
        const ulonglong2* w1 = (const ulonglong2*)(Ws + (k4 * 4 + 1) * 40);
        const ulonglong2* w2 = (const ulonglong2*)(Ws + (k4 * 4 + 2) * 40);
        const ulonglong2* w3 = (const ulonglong2*)(Ws + (k4 * 4 + 3) * 40);
#pragma unroll
        for (int j = 0; j < 10; j++) {
            ulonglong2 a0 = w0[j]; FMA2(acc[2*j], xa, a0.x); FMA2(acc[2*j+1], xa, a0.y);
            ulonglong2 a1 = w1[j]; FMA2(acc[2*j], xb, a1.x); FMA2(acc[2*j+1], xb, a1.y);
            ulonglong2 a2 = w2[j]; FMA2(acc[2*j], xc, a2.x); FMA2(acc[2*j+1], xc, a2.y);
            ulonglong2 a3 = w3[j]; FMA2(acc[2*j], xd, a3.x); FMA2(acc[2*j+1], xd, a3.y);
        }
    }

    float dn = g_dinv[r];
    ull dn2; PACK2(dn2, dn, dn);
#pragma unroll
    for (int j = 0; j < 20; j++) MUL2(acc[j], dn2);

    ulonglong2* Hp = (ulonglong2*)(g_h3 + (size_t)r * 40);
#pragma unroll
    for (int j = 0; j < 10; j++) {
        ulonglong2 v; v.x = acc[2*j]; v.y = acc[2*j+1];
        Hp[j] = v;
    }
}

// -------- gather layer 2 + bias + log_softmax --------
__global__ __launch_bounds__(256) void gather2_k(float* __restrict__ out,
                                                 const float* __restrict__ b2, int N)
{
    int wid = (blockIdx.x * 256 + threadIdx.x) >> 5;
    int lane = threadIdx.x & 31;
    if (wid >= N) return;
    int n = wid;
    bool act = lane < 20;
    int fo = act ? lane * 2 : 0;

    int deg = min(g_cnt[n], CAP);
    const int* bp = g_bkt + (size_t)n * CAP;

    float2 a0 = make_float2(0.f, 0.f), a1 = make_float2(0.f, 0.f);
    float2 a2 = make_float2(0.f, 0.f), a3 = make_float2(0.f, 0.f);
    int e = 0;
    for (; e + 3 < deg; e += 4) {
        int4 ss = *(const int4*)(bp + e);
        float2 v0 = *(const float2*)(g_h3 + (size_t)ss.x * 40 + fo);
        float2 v1 = *(const float2*)(g_h3 + (size_t)ss.y * 40 + fo);
        float2 v2 = *(const float2*)(g_h3 + (size_t)ss.z * 40 + fo);
        float2 v3 = *(const float2*)(g_h3 + (size_t)ss.w * 40 + fo);
        a0.x += v0.x; a0.y += v0.y;
        a1.x += v1.x; a1.y += v1.y;
        a2.x += v2.x; a2.y += v2.y;
        a3.x += v3.x; a3.y += v3.y;
    }
    for (; e < deg; e++) {
        int s0 = __ldg(bp + e);
        float2 v0 = *(const float2*)(g_h3 + (size_t)s0 * 40 + fo);
        a0.x += v0.x; a0.y += v0.y;
    }

    float dn = g_dinv[n];
    float2 h = *(const float2*)(g_h3 + (size_t)n * 40 + fo);
    float2 bb = *(const float2*)(b2 + fo);
    float vx = dn * ((a0.x + a1.x) + (a2.x + a3.x) + h.x) + bb.x;
    float vy = dn * ((a0.y + a1.y) + (a2.y + a3.y) + h.y) + bb.y;

    float m = act ? fmaxf(vx, vy) : -3.0e38f;
#pragma unroll
    for (int o = 16; o > 0; o >>= 1) m = fmaxf(m, __shfl_xor_sync(0xFFFFFFFFu, m, o));
    float s = act ? (expf(vx - m) + expf(vy - m)) : 0.f;
#pragma unroll
    for (int o = 16; o > 0; o >>= 1) s += __shfl_xor_sync(0xFFFFFFFFu, s, o);
    float lse = m + logf(s);

    if (act)
        *(float2*)(out + (size_t)n * 40 + fo) = make_float2(vx - lse, vy - lse);
}

extern "C" void kernel_launch(void* const* d_in, const int* in_sizes, int n_in,
                              void* d_out, int out_size)
{
    const float* x  = (const float*)d_in[0];
    const int*   ei = (const int*)d_in[1];      // int32 (JAX x64 disabled)
    const float* W1 = (const float*)d_in[2];
    const float* b1 = (const float*)d_in[3];
    const float* W2 = (const float*)d_in[4];
    const float* b2 = (const float*)d_in[5];
    float* out = (float*)d_out;

    int N = in_sizes[0] / 128;
    int E = in_sizes[1] / 2;
    const int T = 256;

    // setup
    void* cnt_ptr = 0;
    cudaGetSymbolAddress(&cnt_ptr, g_cnt);
    cudaMemsetAsync(cnt_ptr, 0, (size_t)N * sizeof(int));
    cvtW_k<<<1, 256>>>(W1);
    bucket_k<<<(E + T - 1) / T, T>>>(ei, E, N);
    dinv_k<<<(N + T - 1) / T, T>>>(N);

    // layer 1: per-warp-tile HMMA GEMM + unweighted gather
    {
        int warp_tiles = (N + 15) / 16;          // 16 rows per warp
        int blocks = (warp_tiles + 7) / 8;       // 8 warps per block
        gemm1_wmma_k<<<blocks, 256>>>(x, N);
    }
    gather1_k<<<(N * 32 + T - 1) / T, T>>>(b1, N);

    // layer 2
    gemm2_k<<<(N + T - 1) / T, T>>>(W2, N);
    gather2_k<<<(N * 32 + T - 1) / T, T>>>(out, b2, N);
}